// round 2
// baseline (speedup 1.0000x reference)
#include <cuda_runtime.h>
#include <math.h>

#define BB   16
#define NN   2048
#define DD   128
#define NSL  8
#define HH   128
#define RWS  (BB*NSL)            // 128 slot rows
#define EPSV 1e-8f
#define PSTR 132

// ---------------- scratch (__device__ globals: allocation-free) ----------------
__device__ float g_k[BB*NN*DD];          // 16 MB, k == v
__device__ float g_slots[RWS*2*DD];
__device__ float g_mus[RWS*DD];          // mu_s (GRU hidden)
__device__ float g_qmu[RWS*DD];
__device__ float g_inv[RWS*DD];
__device__ float g_pi[RWS];
__device__ float g_gsum[RWS];
__device__ float g_accV[RWS*DD];
__device__ float g_accV2[RWS*DD];

// transposed weights
__device__ float g_WkT[DD*DD];           // [kk][c]
__device__ float g_WqT[DD*DD];           // [c][d]
__device__ float g_WihT[DD*3*DD];        // [c][j]
__device__ float g_WhhT[DD*3*DD];
__device__ float g_W1muT[DD*HH];         // [c][j]
__device__ float g_W2muT[HH*DD];         // [j][d]
__device__ float g_W1oT[2*DD*2*HH];      // [c][j]
__device__ float g_W2oT[2*HH*DD];        // [c][d]

// ---------------- kT: one-time weight transposes ----------------
__global__ void kT(const float* __restrict__ Wk, const float* __restrict__ Wq,
                   const float* __restrict__ Wih, const float* __restrict__ Whh,
                   const float* __restrict__ W1mu, const float* __restrict__ W2mu,
                   const float* __restrict__ W1o, const float* __restrict__ W2o) {
  int tid = blockIdx.x*blockDim.x + threadIdx.x;
  int stride = gridDim.x*blockDim.x;
  for (int i=tid;i<DD*DD;i+=stride){int c=i>>7,kk=i&127; g_WkT[kk*DD+c]=Wk[i];}
  for (int i=tid;i<DD*DD;i+=stride){int d=i>>7,c=i&127;  g_WqT[c*DD+d]=Wq[i];}
  for (int i=tid;i<3*DD*DD;i+=stride){int j=i>>7,c=i&127; g_WihT[c*384+j]=Wih[i]; g_WhhT[c*384+j]=Whh[i];}
  for (int i=tid;i<HH*DD;i+=stride){int j=i>>7,c=i&127;  g_W1muT[c*HH+j]=W1mu[i];}
  for (int i=tid;i<DD*HH;i+=stride){int d=i>>7,j=i&127;  g_W2muT[j*DD+d]=W2mu[i];}
  for (int i=tid;i<2*HH*2*DD;i+=stride){int j=i>>8,c=i&255; g_W1oT[c*256+j]=W1o[i];}
  for (int i=tid;i<DD*2*HH;i+=stride){int d=i>>8,c=i&255; g_W2oT[c*DD+d]=W2o[i];}
}

// ---------------- kA: fused LayerNorm + k = xn @ Wk^T ----------------
// 64 rows/block, 256 threads. xs[64][128] (32KB) + wt[16][128] (8KB) = 40KB static.
__global__ void kA(const float* __restrict__ inp,
                   const float* __restrict__ lng, const float* __restrict__ lnb) {
  __shared__ float xs[64*DD];
  __shared__ float wt[16*DD];
  const int tid = threadIdx.x;
  const int r0blk = blockIdx.x*64;
  for (int idx=tid; idx<64*DD; idx+=256) xs[idx] = inp[(long)r0blk*DD + idx];
  __syncthreads();
  { // LayerNorm: warp w -> rows w*8..w*8+7
    int w = tid>>5, lane = tid&31;
    for (int r=w*8; r<w*8+8; ++r) {
      float x0=xs[r*DD+lane],    x1=xs[r*DD+lane+32];
      float x2=xs[r*DD+lane+64], x3=xs[r*DD+lane+96];
      float s = x0+x1+x2+x3;
      #pragma unroll
      for (int o=16;o;o>>=1) s += __shfl_xor_sync(0xffffffffu,s,o);
      float m = s*(1.f/128.f);
      float d0=x0-m,d1=x1-m,d2=x2-m,d3=x3-m;
      float s2 = d0*d0+d1*d1+d2*d2+d3*d3;
      #pragma unroll
      for (int o=16;o;o>>=1) s2 += __shfl_xor_sync(0xffffffffu,s2,o);
      float rs = rsqrtf(s2*(1.f/128.f)+1e-5f);
      xs[r*DD+lane]    = d0*rs*lng[lane]    + lnb[lane];
      xs[r*DD+lane+32] = d1*rs*lng[lane+32] + lnb[lane+32];
      xs[r*DD+lane+64] = d2*rs*lng[lane+64] + lnb[lane+64];
      xs[r*DD+lane+96] = d3*rs*lng[lane+96] + lnb[lane+96];
    }
  }
  // GEMM: thread -> 8 rows x 4 cols, K tiled by 16
  const int cg = tid&31, rg = tid>>5;
  const int c0 = cg*4, r0 = rg*8;
  float4 acc[8];
  #pragma unroll
  for (int r=0;r<8;++r) acc[r] = make_float4(0.f,0.f,0.f,0.f);
  for (int kt=0; kt<8; ++kt) {
    __syncthreads();
    for (int i=tid; i<16*DD; i+=256) wt[i] = g_WkT[kt*16*DD + i];
    __syncthreads();
    #pragma unroll 4
    for (int kk=0;kk<16;++kk) {
      float4 wv = *(const float4*)&wt[kk*DD+c0];
      int kg = kt*16 + kk;
      #pragma unroll
      for (int r=0;r<8;++r) {
        float xv = xs[(r0+r)*DD+kg];
        acc[r].x = fmaf(xv,wv.x,acc[r].x);
        acc[r].y = fmaf(xv,wv.y,acc[r].y);
        acc[r].z = fmaf(xv,wv.z,acc[r].z);
        acc[r].w = fmaf(xv,wv.w,acc[r].w);
      }
    }
  }
  #pragma unroll
  for (int r=0;r<8;++r)
    *(float4*)&g_k[(long)(r0blk + r0 + r)*DD + c0] = acc[r];
}

// ---------------- k0: slot init + pi init ----------------
__global__ void k0(const float* __restrict__ noise, const float* __restrict__ smu,
                   const float* __restrict__ slsig) {
  int row = blockIdx.x, t = threadIdx.x;   // 128 x 256
  g_slots[row*256+t] = smu[t] + expf(slsig[t])*noise[row*256+t];
  if (row==0 && t<RWS) g_pi[t] = 1.f/(float)NSL;
}

// ---------------- block reduce helper (nw warps) ----------------
__device__ __forceinline__ float blkSum(float v, float* red, int tid, int nw) {
  int lane = tid&31, w = tid>>5;
  #pragma unroll
  for (int o=16;o;o>>=1) v += __shfl_xor_sync(0xffffffffu,v,o);
  if (lane==0) red[w] = v;
  __syncthreads();
  float tot = 0.f;
  for (int i=0;i<nw;++i) tot += red[i];
  __syncthreads();
  return tot;
}

// ---------------- kQ: per-slot LN + Wq + zero accumulators ----------------
// 128 blocks (= slot rows), 128 threads
__global__ void kQ(const float* __restrict__ lsg, const float* __restrict__ lsb) {
  __shared__ float sn[256];
  __shared__ float red[4];
  int r = blockIdx.x, t = threadIdx.x;
  float x0 = g_slots[r*256+t], x1 = g_slots[r*256+128+t];
  float m = blkSum(x0+x1, red, t, 4) * (1.f/256.f);
  float d0 = x0-m, d1 = x1-m;
  float var = blkSum(d0*d0+d1*d1, red, t, 4) * (1.f/256.f);
  float rs = rsqrtf(var + 1e-5f);
  sn[t]     = d0*rs*lsg[t]     + lsb[t];
  sn[t+128] = d1*rs*lsg[t+128] + lsb[t+128];
  __syncthreads();
  float qmu = 0.f, qls = 0.f;
  #pragma unroll 4
  for (int c=0;c<128;++c) {
    float wv = g_WqT[c*DD+t];
    qmu = fmaf(sn[c],     wv, qmu);
    qls = fmaf(sn[128+c], wv, qls);
  }
  g_qmu[r*DD+t] = qmu;
  g_inv[r*DD+t] = expf(-2.f*qls);
  g_mus[r*DD+t] = sn[t];
  g_accV[r*DD+t] = 0.f;
  g_accV2[r*DD+t] = 0.f;
  if (t==0) g_gsum[r] = 0.f;
}

// ---------------- kP: fused dots/gamma/moment-accumulation pass ----------------
// grid (16 b, 16 chunks), 256 threads; each block: 128 rows of n in 4 tiles of 32
__global__ void kP() {
  __shared__ float ks[32*PSTR];
  __shared__ float qm[8*PSTR];
  __shared__ float iv[8*PSTR];
  __shared__ float gam[8*36];
  __shared__ float spi[8];
  __shared__ float sgs[8];
  int b = blockIdx.x, chunk = blockIdx.y;
  int tid = threadIdx.x, lane = tid&31, w = tid>>5;
  for (int i=tid; i<8*DD; i+=256) {
    int s = i>>7, d = i&127;
    qm[s*PSTR+d] = g_qmu[(b*8+s)*DD+d];
    iv[s*PSTR+d] = g_inv[(b*8+s)*DD+d];
  }
  if (tid<8) { spi[tid] = g_pi[b*8+tid]; sgs[tid] = 0.f; }
  int slot = lane&7, rloc = lane>>3;
  float accV[4] = {0,0,0,0}, acc2[4] = {0,0,0,0};
  float gpart = 0.f;
  int kbase = b*NN*DD + chunk*128*DD;
  for (int tile=0; tile<4; ++tile) {
    __syncthreads();
    for (int i=tid; i<32*DD; i+=256) {
      int rr = i>>7, c = i&127;
      ks[rr*PSTR+c] = g_k[kbase + tile*32*DD + rr*DD + c];
    }
    __syncthreads();
    { // gamma phase: warp w -> rows w*4..w*4+3; lane -> (row=w*4+rloc, slot)
      int row = w*4 + rloc;
      const float* kr = &ks[row*PSTR];
      const float* qs = &qm[slot*PSTR];
      const float* is = &iv[slot*PSTR];
      float dot = 0.f;
      #pragma unroll 8
      for (int d=0; d<128; ++d) {
        float df = kr[d] - qs[d];
        dot = fmaf(is[d]*df, df, dot);
      }
      float e = (expf(-dot) + EPSV) * spi[slot];
      float ssum = e;
      ssum += __shfl_xor_sync(0xffffffffu, ssum, 1);
      ssum += __shfl_xor_sync(0xffffffffu, ssum, 2);
      ssum += __shfl_xor_sync(0xffffffffu, ssum, 4);
      float g = e / ssum;
      gam[slot*36 + row] = g;
      gpart += g;
    }
    __syncthreads();
    { // accum phase: warp w == slot w; lane covers d = lane + 32p
      const float* gr = &gam[w*36];
      #pragma unroll 4
      for (int n=0; n<32; ++n) {
        float g = gr[n];
        #pragma unroll
        for (int p=0;p<4;++p) {
          float kv = ks[n*PSTR + lane + 32*p];
          accV[p] = fmaf(g, kv, accV[p]);
          acc2[p] = fmaf(g*kv, kv, acc2[p]);
        }
      }
    }
  }
  // gsum: lanes {slot, slot+8, slot+16, slot+24} hold partials for same slot
  gpart += __shfl_xor_sync(0xffffffffu, gpart, 8);
  gpart += __shfl_xor_sync(0xffffffffu, gpart, 16);
  if (lane<8) atomicAdd(&sgs[slot], gpart);
  int r = b*8 + w;
  #pragma unroll
  for (int p=0;p<4;++p) {
    atomicAdd(&g_accV [r*DD + lane + 32*p], accV[p]);
    atomicAdd(&g_accV2[r*DD + lane + 32*p], acc2[p]);
  }
  __syncthreads();
  if (tid<8) atomicAdd(&g_gsum[b*8+tid], sgs[tid]);
}

// ---------------- kU: GRU + LN + MLP + logsigma update ----------------
// 128 blocks (slot rows), 128 threads
__global__ void kU(const float* __restrict__ bih, const float* __restrict__ bhh,
                   const float* __restrict__ b1, const float* __restrict__ b2,
                   const float* __restrict__ lmg, const float* __restrict__ lmb) {
  __shared__ float s1s[128];
  __shared__ float mus[128];
  __shared__ float hs[128];
  __shared__ float m1[128];
  __shared__ float red[4];
  int r = blockIdx.x, t = threadIdx.x;
  float gsum = g_gsum[r];
  float s1 = g_accV[r*DD+t]/gsum;
  float s2 = g_accV2[r*DD+t]/gsum;
  float mu = g_mus[r*DD+t];
  s1s[t] = s1; mus[t] = mu;
  __syncthreads();
  float gir=bih[t], giz=bih[128+t], gin=bih[256+t];
  float ghr=bhh[t], ghz=bhh[128+t], ghn=bhh[256+t];
  #pragma unroll 4
  for (int c=0;c<128;++c) {
    float xv = s1s[c], hv = mus[c];
    const float* wi = &g_WihT[c*384];
    const float* wh = &g_WhhT[c*384];
    gir = fmaf(xv, wi[t],     gir);  ghr = fmaf(hv, wh[t],     ghr);
    giz = fmaf(xv, wi[128+t], giz);  ghz = fmaf(hv, wh[128+t], ghz);
    gin = fmaf(xv, wi[256+t], gin);  ghn = fmaf(hv, wh[256+t], ghn);
  }
  float rg = 1.f/(1.f+expf(-(gir+ghr)));
  float zg = 1.f/(1.f+expf(-(giz+ghz)));
  float ng = tanhf(gin + rg*ghn);
  float upd1 = (1.f-zg)*ng + zg*mu;
  // LN(upd1)
  float m = blkSum(upd1, red, t, 4) * (1.f/128.f);
  float dv = upd1 - m;
  float var = blkSum(dv*dv, red, t, 4) * (1.f/128.f);
  float rs = rsqrtf(var + 1e-5f);
  hs[t] = dv*rs*lmg[t] + lmb[t];
  __syncthreads();
  float a1 = b1[t];
  #pragma unroll 4
  for (int c=0;c<128;++c) a1 = fmaf(hs[c], g_W1muT[c*HH+t], a1);
  m1[t] = fmaxf(a1, 0.f);
  __syncthreads();
  float out = upd1 + b2[t];
  #pragma unroll 4
  for (int j=0;j<128;++j) out = fmaf(m1[j], g_W2muT[j*DD+t], out);
  float ls = 0.5f*logf(s2 - 2.f*out*s1 + out*out + EPSV);
  g_slots[r*256+t] = out;
  g_slots[r*256+128+t] = ls;
  if (t==0) g_pi[r] = gsum;
}

// ---------------- kF: final output MLP ----------------
// 128 blocks (slot rows), 256 threads
__global__ void kF(const float* __restrict__ b1o, const float* __restrict__ b2o,
                   float* __restrict__ out) {
  __shared__ float s[256];
  __shared__ float h[256];
  int r = blockIdx.x, t = threadIdx.x;
  s[t] = g_slots[r*256+t];
  __syncthreads();
  float a = b1o[t];
  #pragma unroll 4
  for (int c=0;c<256;++c) a = fmaf(s[c], g_W1oT[c*256+t], a);
  h[t] = fmaxf(a, 0.f);
  __syncthreads();
  if (t < 128) {
    float o = b2o[t];
    #pragma unroll 4
    for (int c=0;c<256;++c) o = fmaf(h[c], g_W2oT[c*DD+t], o);
    out[r*DD+t] = o;
  }
}

extern "C" void kernel_launch(void* const* d_in, const int* in_sizes, int n_in,
                              void* d_out, int out_size) {
  const float* inputs  = (const float*)d_in[0];
  const float* noise   = (const float*)d_in[1];
  const float* smu     = (const float*)d_in[2];
  const float* slsig   = (const float*)d_in[3];
  const float* Wq      = (const float*)d_in[4];
  const float* Wk      = (const float*)d_in[5];
  const float* Wih     = (const float*)d_in[6];
  const float* Whh     = (const float*)d_in[7];
  const float* bih     = (const float*)d_in[8];
  const float* bhh     = (const float*)d_in[9];
  const float* W1mu    = (const float*)d_in[10];
  const float* b1mu    = (const float*)d_in[11];
  const float* W2mu    = (const float*)d_in[12];
  const float* b2mu    = (const float*)d_in[13];
  const float* ln_in_g = (const float*)d_in[14];
  const float* ln_in_b = (const float*)d_in[15];
  const float* lsg     = (const float*)d_in[16];
  const float* lsb     = (const float*)d_in[17];
  const float* lmg     = (const float*)d_in[18];
  const float* lmb     = (const float*)d_in[19];
  const float* W1o     = (const float*)d_in[20];
  const float* b1o     = (const float*)d_in[21];
  const float* W2o     = (const float*)d_in[22];
  const float* b2o     = (const float*)d_in[23];
  float* out = (float*)d_out;

  kT<<<64, 256>>>(Wk, Wq, Wih, Whh, W1mu, W2mu, W1o, W2o);
  kA<<<(BB*NN)/64, 256>>>(inputs, ln_in_g, ln_in_b);
  k0<<<RWS, 256>>>(noise, smu, slsig);
  for (int it=0; it<4; ++it) {
    kQ<<<RWS, 128>>>(lsg, lsb);
    kP<<<dim3(BB, NN/128), 256>>>();
    kU<<<RWS, 128>>>(bih, bhh, b1mu, b2mu, lmg, lmb);
  }
  kF<<<RWS, 256>>>(b1o, b2o, out);
}

// round 3
// speedup vs baseline: 1.4794x; 1.4794x over previous
#include <cuda_runtime.h>
#include <math.h>

#define BB   16
#define NN   2048
#define DD   128
#define NSL  8
#define HH   128
#define RWS  (BB*NSL)            // 128 slot rows
#define EPSV 1e-8f
#define PSTR 132

// ---------------- scratch (__device__ globals: allocation-free) ----------------
__device__ float g_k[BB*NN*DD];          // 16 MB, k == v
__device__ float g_mus[RWS*DD];          // mu_s (GRU hidden)
__device__ float g_qmu[RWS*DD];
__device__ float g_inv[RWS*DD];
__device__ float g_pi[RWS];
__device__ float g_gsum[RWS];
__device__ float g_accV[RWS*DD];
__device__ float g_accV2[RWS*DD];

// transposed weights
__device__ float g_WkT[DD*DD];           // [kk][c]
__device__ float g_WqT[DD*DD];           // [c][d]
__device__ float g_WihT[DD*3*DD];        // [c][j]
__device__ float g_WhhT[DD*3*DD];
__device__ float g_W1muT[DD*HH];         // [c][j]
__device__ float g_W2muT[HH*DD];         // [j][d]
__device__ float g_W1oT[2*DD*2*HH];      // [c][j]
__device__ float g_W2oT[2*HH*DD];        // [c][d]

// ---------------- kT: one-time weight transposes ----------------
__global__ void kT(const float* __restrict__ Wk, const float* __restrict__ Wq,
                   const float* __restrict__ Wih, const float* __restrict__ Whh,
                   const float* __restrict__ W1mu, const float* __restrict__ W2mu,
                   const float* __restrict__ W1o, const float* __restrict__ W2o) {
  int tid = blockIdx.x*blockDim.x + threadIdx.x;
  int stride = gridDim.x*blockDim.x;
  for (int i=tid;i<DD*DD;i+=stride){int c=i>>7,kk=i&127; g_WkT[kk*DD+c]=Wk[i];}
  for (int i=tid;i<DD*DD;i+=stride){int d=i>>7,c=i&127;  g_WqT[c*DD+d]=Wq[i];}
  for (int i=tid;i<3*DD*DD;i+=stride){int j=i>>7,c=i&127; g_WihT[c*384+j]=Wih[i]; g_WhhT[c*384+j]=Whh[i];}
  for (int i=tid;i<HH*DD;i+=stride){int j=i>>7,c=i&127;  g_W1muT[c*HH+j]=W1mu[i];}
  for (int i=tid;i<DD*HH;i+=stride){int d=i>>7,j=i&127;  g_W2muT[j*DD+d]=W2mu[i];}
  for (int i=tid;i<2*HH*2*DD;i+=stride){int j=i>>8,c=i&255; g_W1oT[c*256+j]=W1o[i];}
  for (int i=tid;i<DD*2*HH;i+=stride){int d=i>>8,c=i&255; g_W2oT[c*DD+d]=W2o[i];}
}

// ---------------- kA: fused LayerNorm + k = xn @ Wk^T ----------------
__global__ void kA(const float* __restrict__ inp,
                   const float* __restrict__ lng, const float* __restrict__ lnb) {
  __shared__ float xs[64*DD];
  __shared__ float wt[16*DD];
  const int tid = threadIdx.x;
  const int r0blk = blockIdx.x*64;
  for (int idx=tid; idx<64*DD; idx+=256) xs[idx] = inp[(long)r0blk*DD + idx];
  __syncthreads();
  { // LayerNorm: warp w -> rows w*8..w*8+7
    int w = tid>>5, lane = tid&31;
    for (int r=w*8; r<w*8+8; ++r) {
      float x0=xs[r*DD+lane],    x1=xs[r*DD+lane+32];
      float x2=xs[r*DD+lane+64], x3=xs[r*DD+lane+96];
      float s = x0+x1+x2+x3;
      #pragma unroll
      for (int o=16;o;o>>=1) s += __shfl_xor_sync(0xffffffffu,s,o);
      float m = s*(1.f/128.f);
      float d0=x0-m,d1=x1-m,d2=x2-m,d3=x3-m;
      float s2 = d0*d0+d1*d1+d2*d2+d3*d3;
      #pragma unroll
      for (int o=16;o;o>>=1) s2 += __shfl_xor_sync(0xffffffffu,s2,o);
      float rs = rsqrtf(s2*(1.f/128.f)+1e-5f);
      xs[r*DD+lane]    = d0*rs*lng[lane]    + lnb[lane];
      xs[r*DD+lane+32] = d1*rs*lng[lane+32] + lnb[lane+32];
      xs[r*DD+lane+64] = d2*rs*lng[lane+64] + lnb[lane+64];
      xs[r*DD+lane+96] = d3*rs*lng[lane+96] + lnb[lane+96];
    }
  }
  const int cg = tid&31, rg = tid>>5;
  const int c0 = cg*4, r0 = rg*8;
  float4 acc[8];
  #pragma unroll
  for (int r=0;r<8;++r) acc[r] = make_float4(0.f,0.f,0.f,0.f);
  for (int kt=0; kt<8; ++kt) {
    __syncthreads();
    for (int i=tid; i<16*DD; i+=256) wt[i] = g_WkT[kt*16*DD + i];
    __syncthreads();
    #pragma unroll 4
    for (int kk=0;kk<16;++kk) {
      float4 wv = *(const float4*)&wt[kk*DD+c0];
      int kg = kt*16 + kk;
      #pragma unroll
      for (int r=0;r<8;++r) {
        float xv = xs[(r0+r)*DD+kg];
        acc[r].x = fmaf(xv,wv.x,acc[r].x);
        acc[r].y = fmaf(xv,wv.y,acc[r].y);
        acc[r].z = fmaf(xv,wv.z,acc[r].z);
        acc[r].w = fmaf(xv,wv.w,acc[r].w);
      }
    }
  }
  #pragma unroll
  for (int r=0;r<8;++r)
    *(float4*)&g_k[(long)(r0blk + r0 + r)*DD + c0] = acc[r];
}

// ---------------- 8-warp block reduce ----------------
__device__ __forceinline__ float blkSum8(float v, float* red, int tid) {
  int lane = tid&31, w = tid>>5;
  #pragma unroll
  for (int o=16;o;o>>=1) v += __shfl_xor_sync(0xffffffffu,v,o);
  if (lane==0) red[w] = v;
  __syncthreads();
  float tot = red[0]+red[1]+red[2]+red[3]+red[4]+red[5]+red[6]+red[7];
  __syncthreads();
  return tot;
}

// ---------------- Q-phase (shared by kInit / kUQ) ----------------
// sv: raw 256-dim slot row in smem; sn: scratch 256; 256 threads.
__device__ __forceinline__ void qphase(int r, const float* sv, float* sn, float* red,
                                       const float* __restrict__ lsg,
                                       const float* __restrict__ lsb, int t) {
  float x = sv[t];
  float m = blkSum8(x, red, t) * (1.f/256.f);
  float dv = x - m;
  float var = blkSum8(dv*dv, red, t) * (1.f/256.f);
  float rs = rsqrtf(var + 1e-5f);
  sn[t] = dv*rs*lsg[t] + lsb[t];
  __syncthreads();
  int idx = t & 127, base = (t < 128) ? 0 : 128;
  const float* s = &sn[base];
  float acc = 0.f;
  #pragma unroll 8
  for (int c=0;c<128;++c) acc = fmaf(s[c], g_WqT[c*DD+idx], acc);
  if (t < 128) {
    g_qmu[r*DD+t] = acc;
    g_mus[r*DD+t] = sn[t];
    g_accV[r*DD+t] = 0.f;
    g_accV2[r*DD+t] = 0.f;
  } else {
    g_inv[r*DD+idx] = expf(-2.f*acc);
  }
  if (t==0) g_gsum[r] = 0.f;
}

// ---------------- kInit: slot init + pi + first Q-phase ----------------
__global__ void kInit(const float* __restrict__ noise, const float* __restrict__ smu,
                      const float* __restrict__ slsig,
                      const float* __restrict__ lsg, const float* __restrict__ lsb) {
  __shared__ float sv[256];
  __shared__ float sn[256];
  __shared__ float red[8];
  int r = blockIdx.x, t = threadIdx.x;
  sv[t] = smu[t] + expf(slsig[t])*noise[r*256+t];
  if (t==0) g_pi[r] = 1.f/(float)NSL;
  __syncthreads();
  qphase(r, sv, sn, red, lsg, lsb, t);
}

// ---------------- kP: fused dots/gamma/moment-accumulation pass ----------------
__global__ void kP() {
  __shared__ float ks[32*PSTR];
  __shared__ float qm[8*PSTR];
  __shared__ float iv[8*PSTR];
  __shared__ float gam[8*36];
  __shared__ float spi[8];
  __shared__ float sgs[8];
  int b = blockIdx.x, chunk = blockIdx.y;
  int tid = threadIdx.x, lane = tid&31, w = tid>>5;
  for (int i=tid; i<8*DD; i+=256) {
    int s = i>>7, d = i&127;
    qm[s*PSTR+d] = g_qmu[(b*8+s)*DD+d];
    iv[s*PSTR+d] = g_inv[(b*8+s)*DD+d];
  }
  if (tid<8) { spi[tid] = g_pi[b*8+tid]; sgs[tid] = 0.f; }
  int slot = lane&7, rloc = lane>>3;
  float accV[4] = {0,0,0,0}, acc2[4] = {0,0,0,0};
  float gpart = 0.f;
  int kbase = b*NN*DD + chunk*128*DD;
  for (int tile=0; tile<4; ++tile) {
    __syncthreads();
    for (int i=tid; i<32*DD; i+=256) {
      int rr = i>>7, c = i&127;
      ks[rr*PSTR+c] = g_k[kbase + tile*32*DD + rr*DD + c];
    }
    __syncthreads();
    {
      int row = w*4 + rloc;
      const float* kr = &ks[row*PSTR];
      const float* qs = &qm[slot*PSTR];
      const float* is = &iv[slot*PSTR];
      float dot = 0.f;
      #pragma unroll 8
      for (int d=0; d<128; ++d) {
        float df = kr[d] - qs[d];
        dot = fmaf(is[d]*df, df, dot);
      }
      float e = (expf(-dot) + EPSV) * spi[slot];
      float ssum = e;
      ssum += __shfl_xor_sync(0xffffffffu, ssum, 1);
      ssum += __shfl_xor_sync(0xffffffffu, ssum, 2);
      ssum += __shfl_xor_sync(0xffffffffu, ssum, 4);
      float g = e / ssum;
      gam[slot*36 + row] = g;
      gpart += g;
    }
    __syncthreads();
    {
      const float* gr = &gam[w*36];
      #pragma unroll 4
      for (int n=0; n<32; ++n) {
        float g = gr[n];
        #pragma unroll
        for (int p=0;p<4;++p) {
          float kv = ks[n*PSTR + lane + 32*p];
          accV[p] = fmaf(g, kv, accV[p]);
          acc2[p] = fmaf(g*kv, kv, acc2[p]);
        }
      }
    }
  }
  gpart += __shfl_xor_sync(0xffffffffu, gpart, 8);
  gpart += __shfl_xor_sync(0xffffffffu, gpart, 16);
  if (lane<8) atomicAdd(&sgs[slot], gpart);
  int r = b*8 + w;
  #pragma unroll
  for (int p=0;p<4;++p) {
    atomicAdd(&g_accV [r*DD + lane + 32*p], accV[p]);
    atomicAdd(&g_accV2[r*DD + lane + 32*p], acc2[p]);
  }
  __syncthreads();
  if (tid<8) atomicAdd(&g_gsum[b*8+tid], sgs[tid]);
}

// ---------------- kUQ: GRU + LN + MLP + logsigma, then Q-phase (or final MLP) ----
// 128 blocks (slot rows), 256 threads; contraction dims split across thread halves
__global__ void kUQ(const float* __restrict__ bih, const float* __restrict__ bhh,
                    const float* __restrict__ b1, const float* __restrict__ b2,
                    const float* __restrict__ lmg, const float* __restrict__ lmb,
                    const float* __restrict__ lsg, const float* __restrict__ lsb,
                    const float* __restrict__ b1o, const float* __restrict__ b2o,
                    float* __restrict__ outp, int last) {
  __shared__ float s1s[128], s2s[128], mus[128];
  __shared__ float ps[6*256];
  __shared__ float hs[128];
  __shared__ float m1[128];
  __shared__ float sv[256];
  __shared__ float sn[256];
  __shared__ float red[8];
  int r = blockIdx.x, t = threadIdx.x, tt = t & 127, th = t >> 7;
  float gsum = g_gsum[r];
  if (t < 128) {
    float inv = 1.f/gsum;
    s1s[t] = g_accV[r*DD+t]*inv;
    s2s[t] = g_accV2[r*DD+t]*inv;
    mus[t] = g_mus[r*DD+t];
  }
  __syncthreads();
  // GRU gates: thread (th,tt) covers c in [th*64, th*64+64)
  {
    float gir=0,giz=0,gin=0,ghr=0,ghz=0,ghn=0;
    int c0 = th*64;
    #pragma unroll 8
    for (int c=c0; c<c0+64; ++c) {
      float xv = s1s[c], hv = mus[c];
      const float* wi = &g_WihT[c*384];
      const float* wh = &g_WhhT[c*384];
      gir = fmaf(xv, wi[tt],     gir);  ghr = fmaf(hv, wh[tt],     ghr);
      giz = fmaf(xv, wi[128+tt], giz);  ghz = fmaf(hv, wh[128+tt], ghz);
      gin = fmaf(xv, wi[256+tt], gin);  ghn = fmaf(hv, wh[256+tt], ghn);
    }
    ps[t]=gir; ps[256+t]=giz; ps[512+t]=gin;
    ps[768+t]=ghr; ps[1024+t]=ghz; ps[1280+t]=ghn;
  }
  __syncthreads();
  float upd1 = 0.f;
  if (t < 128) {
    float Gir = ps[t]+ps[t+128]       + bih[t];
    float Giz = ps[256+t]+ps[384+t]   + bih[128+t];
    float Gin = ps[512+t]+ps[640+t]   + bih[256+t];
    float Ghr = ps[768+t]+ps[896+t]   + bhh[t];
    float Ghz = ps[1024+t]+ps[1152+t] + bhh[128+t];
    float Ghn = ps[1280+t]+ps[1408+t] + bhh[256+t];
    float rg = 1.f/(1.f+expf(-(Gir+Ghr)));
    float zg = 1.f/(1.f+expf(-(Giz+Ghz)));
    float ng = tanhf(Gin + rg*Ghn);
    upd1 = (1.f-zg)*ng + zg*mus[t];
  }
  __syncthreads();
  // LN(upd1) over 128 (inactive threads contribute 0)
  {
    float v = (t<128) ? upd1 : 0.f;
    float m = blkSum8(v, red, t) * (1.f/128.f);
    float dv = (t<128) ? (upd1 - m) : 0.f;
    float var = blkSum8(dv*dv, red, t) * (1.f/128.f);
    float rs = rsqrtf(var + 1e-5f);
    if (t<128) hs[t] = dv*rs*lmg[t] + lmb[t];
  }
  __syncthreads();
  // MLP1: split c over halves
  {
    float a = 0.f;
    int c0 = th*64;
    #pragma unroll 8
    for (int c=c0; c<c0+64; ++c) a = fmaf(hs[c], g_W1muT[c*HH+tt], a);
    ps[t] = a;
  }
  __syncthreads();
  if (t < 128) m1[t] = fmaxf(ps[t]+ps[t+128]+b1[t], 0.f);
  __syncthreads();
  // MLP2: split j over halves
  {
    float a = 0.f;
    int j0 = th*64;
    #pragma unroll 8
    for (int j=j0; j<j0+64; ++j) a = fmaf(m1[j], g_W2muT[j*DD+tt], a);
    ps[t] = a;
  }
  __syncthreads();
  if (t < 128) {
    float out = upd1 + b2[t] + ps[t] + ps[t+128];
    float ls = 0.5f*logf(s2s[t] - 2.f*out*s1s[t] + out*out + EPSV);
    sv[t] = out;
    sv[128+t] = ls;
    if (t==0) g_pi[r] = gsum;
  }
  __syncthreads();
  if (!last) {
    qphase(r, sv, sn, red, lsg, lsb, t);
  } else {
    // final output MLP: h = relu(sv @ W1o^T + b1o), out = h @ W2o^T + b2o
    float a = b1o[t];
    #pragma unroll 8
    for (int c=0;c<256;++c) a = fmaf(sv[c], g_W1oT[c*256+t], a);
    sn[t] = fmaxf(a, 0.f);
    __syncthreads();
    if (t < 128) {
      float o = b2o[t];
      #pragma unroll 8
      for (int c=0;c<256;++c) o = fmaf(sn[c], g_W2oT[c*DD+t], o);
      outp[r*DD+t] = o;
    }
  }
}

extern "C" void kernel_launch(void* const* d_in, const int* in_sizes, int n_in,
                              void* d_out, int out_size) {
  const float* inputs  = (const float*)d_in[0];
  const float* noise   = (const float*)d_in[1];
  const float* smu     = (const float*)d_in[2];
  const float* slsig   = (const float*)d_in[3];
  const float* Wq      = (const float*)d_in[4];
  const float* Wk      = (const float*)d_in[5];
  const float* Wih     = (const float*)d_in[6];
  const float* Whh     = (const float*)d_in[7];
  const float* bih     = (const float*)d_in[8];
  const float* bhh     = (const float*)d_in[9];
  const float* W1mu    = (const float*)d_in[10];
  const float* b1mu    = (const float*)d_in[11];
  const float* W2mu    = (const float*)d_in[12];
  const float* b2mu    = (const float*)d_in[13];
  const float* ln_in_g = (const float*)d_in[14];
  const float* ln_in_b = (const float*)d_in[15];
  const float* lsg     = (const float*)d_in[16];
  const float* lsb     = (const float*)d_in[17];
  const float* lmg     = (const float*)d_in[18];
  const float* lmb     = (const float*)d_in[19];
  const float* W1o     = (const float*)d_in[20];
  const float* b1o     = (const float*)d_in[21];
  const float* W2o     = (const float*)d_in[22];
  const float* b2o     = (const float*)d_in[23];
  float* out = (float*)d_out;

  kT<<<64, 256>>>(Wk, Wq, Wih, Whh, W1mu, W2mu, W1o, W2o);
  kA<<<(BB*NN)/64, 256>>>(inputs, ln_in_g, ln_in_b);
  kInit<<<RWS, 256>>>(noise, smu, slsig, lsg, lsb);
  for (int it=0; it<4; ++it) {
    kP<<<dim3(BB, NN/128), 256>>>();
    kUQ<<<RWS, 256>>>(bih, bhh, b1mu, b2mu, lmg, lmb, lsg, lsb,
                      b1o, b2o, out, it==3 ? 1 : 0);
  }
}